// round 11
// baseline (speedup 1.0000x reference)
#include <cuda_runtime.h>

// ---------------- problem constants ----------------
#define N_EC   100000
#define N_DG   400000
#define N_CA3  120000
#define N_CA1  100000
#define T_STEPS 4
#define DT_     0.5f
#define A_IZH   0.02f
#define B_IZH   0.2f
#define TAU_I   0.9f
#define THR_I   1.0f
#define INH_GAIN 2.0f

#define TPB 256
#define NG  (N_EC / 4)              // 25000 float4 groups (out has the same count)
#define NB  ((NG + TPB - 1) / TPB)  // 98 CTAs: exactly one group per thread

// ---------------- persistent device state ----------------
// fallback-only per-neuron state
__device__ float g_ec_v[N_EC],  g_ec_u[N_EC],  g_ec_s[N_EC];
__device__ float g_dg_v[N_DG],  g_dg_u[N_DG],  g_dg_s[N_DG],  g_dg_I[N_DG];
__device__ float g_c3_v[N_CA3], g_c3_u[N_CA3], g_c3_s[N_CA3], g_c3_I[N_CA3];
__device__ float g_c1_v[N_CA1], g_c1_u[N_CA1],                g_c1_I[N_CA1];

__device__ int      g_flag = 0;        // any-spike flag  (invariant: 0 at entry/exit)
__device__ unsigned g_arrive = 0;      // arrival counter (invariant: 0 at entry/exit)

// ---------------- fast-path izh step: spike DETECTION only ----------------
// After a spike the trajectory no longer needs to be exact (the flag forces the
// exact fallback), so no c/d loads and no reset here.
__device__ __forceinline__ void istep(float& v, float& u, float I, bool& any) {
    v += (0.04f * v * v + 5.f * v + 140.f - u + I) * DT_;
    v = fminf(fmaxf(v, -90.f), 40.f);
    u += A_IZH * (B_IZH * v - u) * DT_;
    any |= (v >= 30.f);
}

// ---------------- exact fallback helpers (single block; cold path) ----------------
__device__ void fb_trans(int nnz, const int* __restrict__ src, const int* __restrict__ tgt,
                         const float* __restrict__ val, const float* __restrict__ spk,
                         float* __restrict__ Iarr, float* sum)
{
    float local = 0.f;
    for (int e = threadIdx.x; e < nnz; e += TPB) {
        float s = spk[src[e]];
        if (s != 0.f) { float w = val[e] * s; atomicAdd(&Iarr[tgt[e]], w); local += w; }
    }
    #pragma unroll
    for (int o = 16; o; o >>= 1) local += __shfl_down_sync(0xffffffffu, local, o);
    if ((threadIdx.x & 31) == 0 && local != 0.f) atomicAdd(sum, local);
}

__device__ void fb_pop(int nc, float* v, float* u, const float* c, const float* d,
                       float* Iarr, float* s, float* sum, float* iv, float nrm, float* outv)
{
    // scalar inhibitory LIF (whole inhibitory population is one scalar:
    // identical input jnp.full(mean) from identical zero init)
    float mean = *sum * nrm;
    float ivn  = TAU_I * (*iv) + (1.f - TAU_I) * mean;
    float spI  = (ivn >= THR_I) ? 1.f : 0.f;
    float inh  = INH_GAIN * spI;
    __syncthreads();
    if (threadIdx.x == 0) { *iv = (spI > 0.f) ? 0.f : ivn; *sum = 0.f; }
    for (int i = threadIdx.x; i < nc; i += TPB) {
        float I = Iarr[i] - inh;  Iarr[i] = 0.f;
        float vv = v[i], uu = u[i];
        vv += (0.04f * vv * vv + 5.f * vv + 140.f - uu + I) * DT_;
        vv = fminf(fmaxf(vv, -90.f), 40.f);
        uu += A_IZH * (B_IZH * vv - uu) * DT_;   // post-clamp v, matches reference
        bool sp = (vv >= 30.f);
        if (s) s[i] = sp ? 1.f : 0.f;
        if (sp) { vv = c[i]; uu += d[i]; }
        v[i] = vv; u[i] = uu;
        if (outv) outv[i] = vv;
    }
    __syncthreads();
}

// ---------------- the one kernel ----------------
__global__ __launch_bounds__(TPB)
void hippo_kernel(const float* __restrict__ drive,
                  const int* pp_src, const int* pp_tgt, const float* pp_val, int pp_nnz,
                  const int* mf_src, const int* mf_tgt, const float* mf_val, int mf_nnz,
                  const int* rc_src, const int* rc_tgt, const float* rc_val, int rc_nnz,
                  const int* sc_src, const int* sc_tgt, const float* sc_val, int sc_nnz,
                  const float* ec_c, const float* ec_d, const float* dg_c, const float* dg_d,
                  const float* ca3_c, const float* ca3_d, const float* ca1_c, const float* ca1_d,
                  float* __restrict__ out)
{
    const int tid = threadIdx.x;
    const int gt  = blockIdx.x * TPB + tid;

    // ===== fast path: exact zero-spike rollout =====
    bool any = false;

    // DG/CA3/CA1 under zero input + identical init are population-uniform
    // scalar trajectories; no runtime data involved -> fully constant-folded.
    {
        float v = -65.f, u = B_IZH * -65.f;
        #pragma unroll
        for (int t = 0; t < T_STEPS; t++) istep(v, u, 0.f, any);
    }
    {
        float v = -65.f, u = B_IZH * -65.f;
        #pragma unroll
        for (int t = 0; t < T_STEPS; t++) istep(v, u, 0.f, any);
    }
    float c1v;
    {
        float v = -65.f, u = B_IZH * -65.f;
        #pragma unroll
        for (int t = 0; t < T_STEPS; t++) istep(v, u, 0.f, any);
        c1v = v;
    }

    // EC: exactly one float4 group per thread; all 4 timestep loads issued up front
    if (gt < NG) {
        const float4* dr4 = (const float4*)drive;
        float4 D0 = dr4[0 * NG + gt];
        float4 D1 = dr4[1 * NG + gt];
        float4 D2 = dr4[2 * NG + gt];
        float4 D3 = dr4[3 * NG + gt];
        #define EC_LANE(comp) { \
            float v = -65.f, u = B_IZH * -65.f; \
            istep(v, u, D0.comp, any); istep(v, u, D1.comp, any); \
            istep(v, u, D2.comp, any); istep(v, u, D3.comp, any); }
        EC_LANE(x) EC_LANE(y) EC_LANE(z) EC_LANE(w)
        #undef EC_LANE

        // optimistic output (the fallback overwrites it if any spike occurred)
        ((float4*)out)[gt] = make_float4(c1v, c1v, c1v, c1v);
    }

    if (any) g_flag = 1;

    // ===== arrive-only "barrier": non-last blocks exit without waiting =====
    __threadfence();                       // release: out/flag stores before arrive
    __syncthreads();
    __shared__ unsigned s_ticket;
    if (tid == 0) s_ticket = atomicAdd(&g_arrive, 1u);
    __syncthreads();
    if (s_ticket != (unsigned)(NB - 1)) return;   // fast exit: no spinning anywhere

    // ----- last-arriving block: validate -----
    if (tid == 0) g_arrive = 0;            // restore invariant for next replay
    __threadfence();                       // acquire side of the arrive chain
    if (*(volatile int*)&g_flag == 0) return;

    // ===== exact fallback (spikes detected): full sim in this one block =====
    if (tid == 0) g_flag = 0;
    for (int i = tid; i < N_DG; i += TPB) {
        if (i < N_EC)  { g_ec_v[i] = -65.f; g_ec_u[i] = B_IZH * -65.f; g_ec_s[i] = 0.f; }
        g_dg_v[i] = -65.f; g_dg_u[i] = B_IZH * -65.f; g_dg_s[i] = 0.f; g_dg_I[i] = 0.f;
        if (i < N_CA3) { g_c3_v[i] = -65.f; g_c3_u[i] = B_IZH * -65.f; g_c3_s[i] = 0.f; g_c3_I[i] = 0.f; }
        if (i < N_CA1) { g_c1_v[i] = -65.f; g_c1_u[i] = B_IZH * -65.f; g_c1_I[i] = 0.f; }
    }
    __shared__ float s_sum[3], s_iv[3];
    if (tid < 3) { s_sum[tid] = 0.f; s_iv[tid] = 0.f; }
    __syncthreads();

    for (int t = 0; t < T_STEPS; t++) {
        // EC (drive only, no inhibition)
        for (int i = tid; i < N_EC; i += TPB) {
            float v = g_ec_v[i], u = g_ec_u[i];
            v += (0.04f * v * v + 5.f * v + 140.f - u + drive[t * N_EC + i]) * DT_;
            v = fminf(fmaxf(v, -90.f), 40.f);
            u += A_IZH * (B_IZH * v - u) * DT_;
            bool sp = (v >= 30.f);
            g_ec_s[i] = sp ? 1.f : 0.f;
            if (sp) { v = ec_c[i]; u += ec_d[i]; }
            g_ec_v[i] = v; g_ec_u[i] = u;
        }
        __syncthreads();

        fb_trans(pp_nnz, pp_src, pp_tgt, pp_val, g_ec_s, g_dg_I, &s_sum[0]);
        __syncthreads();
        fb_pop(N_DG, g_dg_v, g_dg_u, dg_c, dg_d, g_dg_I, g_dg_s,
               &s_sum[0], &s_iv[0], 1.f / N_DG, nullptr);

        fb_trans(mf_nnz, mf_src, mf_tgt, mf_val, g_dg_s, g_c3_I, &s_sum[1]);
        fb_trans(rc_nnz, rc_src, rc_tgt, rc_val, g_c3_s, g_c3_I, &s_sum[1]);
        __syncthreads();
        fb_pop(N_CA3, g_c3_v, g_c3_u, ca3_c, ca3_d, g_c3_I, g_c3_s,
               &s_sum[1], &s_iv[1], 1.f / N_CA3, nullptr);

        fb_trans(sc_nnz, sc_src, sc_tgt, sc_val, g_c3_s, g_c1_I, &s_sum[2]);
        __syncthreads();
        fb_pop(N_CA1, g_c1_v, g_c1_u, ca1_c, ca1_d, g_c1_I, nullptr,
               &s_sum[2], &s_iv[2], 1.f / N_CA1,
               (t == T_STEPS - 1) ? out : nullptr);
    }
}

// ---------------- launch ----------------
extern "C" void kernel_launch(void* const* d_in, const int* in_sizes, int n_in,
                              void* d_out, int out_size)
{
    const float* drive  = (const float*)d_in[0];
    const int*   pp_src = (const int*)  d_in[1];
    const int*   pp_tgt = (const int*)  d_in[2];
    const float* pp_val = (const float*)d_in[3];
    const int*   mf_src = (const int*)  d_in[4];
    const int*   mf_tgt = (const int*)  d_in[5];
    const float* mf_val = (const float*)d_in[6];
    const int*   rc_src = (const int*)  d_in[7];
    const int*   rc_tgt = (const int*)  d_in[8];
    const float* rc_val = (const float*)d_in[9];
    const int*   sc_src = (const int*)  d_in[10];
    const int*   sc_tgt = (const int*)  d_in[11];
    const float* sc_val = (const float*)d_in[12];
    const float* ec_c  = (const float*)d_in[13];
    const float* ec_d  = (const float*)d_in[14];
    const float* dg_c  = (const float*)d_in[15];
    const float* dg_d  = (const float*)d_in[16];
    const float* ca3_c = (const float*)d_in[17];
    const float* ca3_d = (const float*)d_in[18];
    const float* ca1_c = (const float*)d_in[19];
    const float* ca1_d = (const float*)d_in[20];

    const int pp_nnz = in_sizes[1];
    const int mf_nnz = in_sizes[4];
    const int rc_nnz = in_sizes[7];
    const int sc_nnz = in_sizes[10];

    hippo_kernel<<<NB, TPB>>>(drive,
                              pp_src, pp_tgt, pp_val, pp_nnz,
                              mf_src, mf_tgt, mf_val, mf_nnz,
                              rc_src, rc_tgt, rc_val, rc_nnz,
                              sc_src, sc_tgt, sc_val, sc_nnz,
                              ec_c, ec_d, dg_c, dg_d, ca3_c, ca3_d, ca1_c, ca1_d,
                              (float*)d_out);
}

// round 12
// speedup vs baseline: 1.4583x; 1.4583x over previous
#include <cuda_runtime.h>

// ---------------- problem constants ----------------
#define N_EC   100000
#define N_DG   400000
#define N_CA3  120000
#define N_CA1  100000
#define T_STEPS 4
#define DT_     0.5f
#define A_IZH   0.02f
#define B_IZH   0.2f
#define TAU_I   0.9f
#define THR_I   1.0f
#define INH_GAIN 2.0f

#define TPB 256
#define NG  (N_EC / 4)              // 25000 float4 groups (out has the same count)
#define NB  ((NG + TPB - 1) / TPB)  // 98 CTAs: exactly one group per thread

// ---------------- persistent device state ----------------
// fallback-only per-neuron state
__device__ float g_ec_v[N_EC],  g_ec_u[N_EC],  g_ec_s[N_EC];
__device__ float g_dg_v[N_DG],  g_dg_u[N_DG],  g_dg_s[N_DG],  g_dg_I[N_DG];
__device__ float g_c3_v[N_CA3], g_c3_u[N_CA3], g_c3_s[N_CA3], g_c3_I[N_CA3];
__device__ float g_c1_v[N_CA1], g_c1_u[N_CA1],                g_c1_I[N_CA1];

// packed arrival counter: bits[0:16) = arrivals, bits[16:32) = spike-flag votes
// invariant: 0 at kernel entry/exit
__device__ unsigned g_arrive = 0;

// ---------------- fast-path izh step: spike DETECTION only ----------------
// After a spike the trajectory no longer needs to be exact (the flag forces the
// exact fallback), so no c/d loads and no reset here.
__device__ __forceinline__ void istep(float& v, float& u, float I, bool& any) {
    v += (0.04f * v * v + 5.f * v + 140.f - u + I) * DT_;
    v = fminf(fmaxf(v, -90.f), 40.f);
    u += A_IZH * (B_IZH * v - u) * DT_;
    any |= (v >= 30.f);
}

// ---------------- exact fallback helpers (single block; cold path) ----------------
__device__ void fb_trans(int nnz, const int* __restrict__ src, const int* __restrict__ tgt,
                         const float* __restrict__ val, const float* __restrict__ spk,
                         float* __restrict__ Iarr, float* sum)
{
    float local = 0.f;
    for (int e = threadIdx.x; e < nnz; e += TPB) {
        float s = spk[src[e]];
        if (s != 0.f) { float w = val[e] * s; atomicAdd(&Iarr[tgt[e]], w); local += w; }
    }
    #pragma unroll
    for (int o = 16; o; o >>= 1) local += __shfl_down_sync(0xffffffffu, local, o);
    if ((threadIdx.x & 31) == 0 && local != 0.f) atomicAdd(sum, local);
}

__device__ void fb_pop(int nc, float* v, float* u, const float* c, const float* d,
                       float* Iarr, float* s, float* sum, float* iv, float nrm, float* outv)
{
    // scalar inhibitory LIF (whole inhibitory population is one scalar:
    // identical input jnp.full(mean) from identical zero init)
    float mean = *sum * nrm;
    float ivn  = TAU_I * (*iv) + (1.f - TAU_I) * mean;
    float spI  = (ivn >= THR_I) ? 1.f : 0.f;
    float inh  = INH_GAIN * spI;
    __syncthreads();
    if (threadIdx.x == 0) { *iv = (spI > 0.f) ? 0.f : ivn; *sum = 0.f; }
    for (int i = threadIdx.x; i < nc; i += TPB) {
        float I = Iarr[i] - inh;  Iarr[i] = 0.f;
        float vv = v[i], uu = u[i];
        vv += (0.04f * vv * vv + 5.f * vv + 140.f - uu + I) * DT_;
        vv = fminf(fmaxf(vv, -90.f), 40.f);
        uu += A_IZH * (B_IZH * vv - uu) * DT_;   // post-clamp v, matches reference
        bool sp = (vv >= 30.f);
        if (s) s[i] = sp ? 1.f : 0.f;
        if (sp) { vv = c[i]; uu += d[i]; }
        v[i] = vv; u[i] = uu;
        if (outv) outv[i] = vv;
    }
    __syncthreads();
}

// ---------------- the one kernel ----------------
__global__ __launch_bounds__(TPB)
void hippo_kernel(const float* __restrict__ drive,
                  const int* pp_src, const int* pp_tgt, const float* pp_val, int pp_nnz,
                  const int* mf_src, const int* mf_tgt, const float* mf_val, int mf_nnz,
                  const int* rc_src, const int* rc_tgt, const float* rc_val, int rc_nnz,
                  const int* sc_src, const int* sc_tgt, const float* sc_val, int sc_nnz,
                  const float* ec_c, const float* ec_d, const float* dg_c, const float* dg_d,
                  const float* ca3_c, const float* ca3_d, const float* ca1_c, const float* ca1_d,
                  float* __restrict__ out)
{
    const int tid = threadIdx.x;
    const int gt  = blockIdx.x * TPB + tid;

    // ===== fast path: exact zero-spike rollout =====
    bool any = false;

    // DG/CA3/CA1 under zero input + identical init are population-uniform
    // scalar trajectories; no runtime data involved -> fully constant-folded
    // (c1v and their spike checks become literals).
    {
        float v = -65.f, u = B_IZH * -65.f;
        #pragma unroll
        for (int t = 0; t < T_STEPS; t++) istep(v, u, 0.f, any);
    }
    {
        float v = -65.f, u = B_IZH * -65.f;
        #pragma unroll
        for (int t = 0; t < T_STEPS; t++) istep(v, u, 0.f, any);
    }
    float c1v;
    {
        float v = -65.f, u = B_IZH * -65.f;
        #pragma unroll
        for (int t = 0; t < T_STEPS; t++) istep(v, u, 0.f, any);
        c1v = v;
    }

    if (gt < NG) {
        // optimistic output FIRST: c1v is a literal, so this STG has no
        // dependence on the loads below and drains behind their latency.
        ((float4*)out)[gt] = make_float4(c1v, c1v, c1v, c1v);

        // EC: exactly one float4 group per thread; all 4 timestep loads up front
        const float4* dr4 = (const float4*)drive;
        float4 D0 = dr4[0 * NG + gt];
        float4 D1 = dr4[1 * NG + gt];
        float4 D2 = dr4[2 * NG + gt];
        float4 D3 = dr4[3 * NG + gt];
        #define EC_LANE(comp) { \
            float v = -65.f, u = B_IZH * -65.f; \
            istep(v, u, D0.comp, any); istep(v, u, D1.comp, any); \
            istep(v, u, D2.comp, any); istep(v, u, D3.comp, any); }
        EC_LANE(x) EC_LANE(y) EC_LANE(z) EC_LANE(w)
        #undef EC_LANE
    }

    // ===== packed arrive: flag rides in the same atomic, no g_flag anywhere =====
    unsigned blockAny = __syncthreads_or(any ? 1 : 0);    // barrier + OR in one op
    __shared__ unsigned s_ticket;
    if (tid == 0) {
        __threadfence();                                  // release: out stores before arrive
        s_ticket = atomicAdd(&g_arrive, 1u | (blockAny << 16));
    }
    __syncthreads();
    unsigned ticket = s_ticket;
    if ((ticket & 0xFFFFu) != (unsigned)(NB - 1)) return; // fast exit: no spinning anywhere

    // ----- last-arriving block -----
    if (tid == 0) g_arrive = 0;                           // restore invariant for replay
    if (((ticket >> 16) | blockAny) == 0) return;         // verdict from the atomic itself

    // ===== exact fallback (spikes detected): full sim in this one block =====
    __threadfence();                                      // acquire side of the arrive chain
    for (int i = tid; i < N_DG; i += TPB) {
        if (i < N_EC)  { g_ec_v[i] = -65.f; g_ec_u[i] = B_IZH * -65.f; g_ec_s[i] = 0.f; }
        g_dg_v[i] = -65.f; g_dg_u[i] = B_IZH * -65.f; g_dg_s[i] = 0.f; g_dg_I[i] = 0.f;
        if (i < N_CA3) { g_c3_v[i] = -65.f; g_c3_u[i] = B_IZH * -65.f; g_c3_s[i] = 0.f; g_c3_I[i] = 0.f; }
        if (i < N_CA1) { g_c1_v[i] = -65.f; g_c1_u[i] = B_IZH * -65.f; g_c1_I[i] = 0.f; }
    }
    __shared__ float s_sum[3], s_iv[3];
    if (tid < 3) { s_sum[tid] = 0.f; s_iv[tid] = 0.f; }
    __syncthreads();

    for (int t = 0; t < T_STEPS; t++) {
        // EC (drive only, no inhibition)
        for (int i = tid; i < N_EC; i += TPB) {
            float v = g_ec_v[i], u = g_ec_u[i];
            v += (0.04f * v * v + 5.f * v + 140.f - u + drive[t * N_EC + i]) * DT_;
            v = fminf(fmaxf(v, -90.f), 40.f);
            u += A_IZH * (B_IZH * v - u) * DT_;
            bool sp = (v >= 30.f);
            g_ec_s[i] = sp ? 1.f : 0.f;
            if (sp) { v = ec_c[i]; u += ec_d[i]; }
            g_ec_v[i] = v; g_ec_u[i] = u;
        }
        __syncthreads();

        fb_trans(pp_nnz, pp_src, pp_tgt, pp_val, g_ec_s, g_dg_I, &s_sum[0]);
        __syncthreads();
        fb_pop(N_DG, g_dg_v, g_dg_u, dg_c, dg_d, g_dg_I, g_dg_s,
               &s_sum[0], &s_iv[0], 1.f / N_DG, nullptr);

        fb_trans(mf_nnz, mf_src, mf_tgt, mf_val, g_dg_s, g_c3_I, &s_sum[1]);
        fb_trans(rc_nnz, rc_src, rc_tgt, rc_val, g_c3_s, g_c3_I, &s_sum[1]);
        __syncthreads();
        fb_pop(N_CA3, g_c3_v, g_c3_u, ca3_c, ca3_d, g_c3_I, g_c3_s,
               &s_sum[1], &s_iv[1], 1.f / N_CA3, nullptr);

        fb_trans(sc_nnz, sc_src, sc_tgt, sc_val, g_c3_s, g_c1_I, &s_sum[2]);
        __syncthreads();
        fb_pop(N_CA1, g_c1_v, g_c1_u, ca1_c, ca1_d, g_c1_I, nullptr,
               &s_sum[2], &s_iv[2], 1.f / N_CA1,
               (t == T_STEPS - 1) ? out : nullptr);
    }
}

// ---------------- launch ----------------
extern "C" void kernel_launch(void* const* d_in, const int* in_sizes, int n_in,
                              void* d_out, int out_size)
{
    const float* drive  = (const float*)d_in[0];
    const int*   pp_src = (const int*)  d_in[1];
    const int*   pp_tgt = (const int*)  d_in[2];
    const float* pp_val = (const float*)d_in[3];
    const int*   mf_src = (const int*)  d_in[4];
    const int*   mf_tgt = (const int*)  d_in[5];
    const float* mf_val = (const float*)d_in[6];
    const int*   rc_src = (const int*)  d_in[7];
    const int*   rc_tgt = (const int*)  d_in[8];
    const float* rc_val = (const float*)d_in[9];
    const int*   sc_src = (const int*)  d_in[10];
    const int*   sc_tgt = (const int*)  d_in[11];
    const float* sc_val = (const float*)d_in[12];
    const float* ec_c  = (const float*)d_in[13];
    const float* ec_d  = (const float*)d_in[14];
    const float* dg_c  = (const float*)d_in[15];
    const float* dg_d  = (const float*)d_in[16];
    const float* ca3_c = (const float*)d_in[17];
    const float* ca3_d = (const float*)d_in[18];
    const float* ca1_c = (const float*)d_in[19];
    const float* ca1_d = (const float*)d_in[20];

    const int pp_nnz = in_sizes[1];
    const int mf_nnz = in_sizes[4];
    const int rc_nnz = in_sizes[7];
    const int sc_nnz = in_sizes[10];

    hippo_kernel<<<NB, TPB>>>(drive,
                              pp_src, pp_tgt, pp_val, pp_nnz,
                              mf_src, mf_tgt, mf_val, mf_nnz,
                              rc_src, rc_tgt, rc_val, rc_nnz,
                              sc_src, sc_tgt, sc_val, sc_nnz,
                              ec_c, ec_d, dg_c, dg_d, ca3_c, ca3_d, ca1_c, ca1_d,
                              (float*)d_out);
}

// round 14
// speedup vs baseline: 1.4651x; 1.0047x over previous
#include <cuda_runtime.h>
#include <cuda/atomic>

// ---------------- problem constants ----------------
#define N_EC   100000
#define N_DG   400000
#define N_CA3  120000
#define N_CA1  100000
#define T_STEPS 4
#define DT_     0.5f
#define A_IZH   0.02f
#define B_IZH   0.2f
#define TAU_I   0.9f
#define THR_I   1.0f
#define INH_GAIN 2.0f

#define TPB 256
#define NG  (N_EC / 4)              // 25000 float4 groups (out has the same count)
#define NB  ((NG + TPB - 1) / TPB)  // 98 CTAs: exactly one group per thread

// ---------------- persistent device state ----------------
// fallback-only per-neuron state
__device__ float g_ec_v[N_EC],  g_ec_u[N_EC],  g_ec_s[N_EC];
__device__ float g_dg_v[N_DG],  g_dg_u[N_DG],  g_dg_s[N_DG],  g_dg_I[N_DG];
__device__ float g_c3_v[N_CA3], g_c3_u[N_CA3], g_c3_s[N_CA3], g_c3_I[N_CA3];
__device__ float g_c1_v[N_CA1], g_c1_u[N_CA1],                g_c1_I[N_CA1];

// packed arrival counter: bits[0:16) = arrivals, bits[16:32) = spike-flag votes
// invariant: 0 at kernel entry/exit
__device__ unsigned g_arrive = 0;

// ---------------- fast-path izh step: spike DETECTION only ----------------
// After a spike the trajectory no longer needs to be exact (the flag forces the
// exact fallback), so no c/d loads and no reset here.
__device__ __forceinline__ void istep(float& v, float& u, float I, bool& any) {
    v += (0.04f * v * v + 5.f * v + 140.f - u + I) * DT_;
    v = fminf(fmaxf(v, -90.f), 40.f);
    u += A_IZH * (B_IZH * v - u) * DT_;
    any |= (v >= 30.f);
}

// ---------------- exact fallback helpers (single block; cold path) ----------------
__device__ void fb_trans(int nnz, const int* __restrict__ src, const int* __restrict__ tgt,
                         const float* __restrict__ val, const float* __restrict__ spk,
                         float* __restrict__ Iarr, float* sum)
{
    float local = 0.f;
    for (int e = threadIdx.x; e < nnz; e += TPB) {
        float s = spk[src[e]];
        if (s != 0.f) { float w = val[e] * s; atomicAdd(&Iarr[tgt[e]], w); local += w; }
    }
    #pragma unroll
    for (int o = 16; o; o >>= 1) local += __shfl_down_sync(0xffffffffu, local, o);
    if ((threadIdx.x & 31) == 0 && local != 0.f) atomicAdd(sum, local);
}

__device__ void fb_pop(int nc, float* v, float* u, const float* c, const float* d,
                       float* Iarr, float* s, float* sum, float* iv, float nrm, float* outv)
{
    // scalar inhibitory LIF (whole inhibitory population is one scalar:
    // identical input jnp.full(mean) from identical zero init)
    float mean = *sum * nrm;
    float ivn  = TAU_I * (*iv) + (1.f - TAU_I) * mean;
    float spI  = (ivn >= THR_I) ? 1.f : 0.f;
    float inh  = INH_GAIN * spI;
    __syncthreads();
    if (threadIdx.x == 0) { *iv = (spI > 0.f) ? 0.f : ivn; *sum = 0.f; }
    for (int i = threadIdx.x; i < nc; i += TPB) {
        float I = Iarr[i] - inh;  Iarr[i] = 0.f;
        float vv = v[i], uu = u[i];
        vv += (0.04f * vv * vv + 5.f * vv + 140.f - uu + I) * DT_;
        vv = fminf(fmaxf(vv, -90.f), 40.f);
        uu += A_IZH * (B_IZH * vv - uu) * DT_;   // post-clamp v, matches reference
        bool sp = (vv >= 30.f);
        if (s) s[i] = sp ? 1.f : 0.f;
        if (sp) { vv = c[i]; uu += d[i]; }
        v[i] = vv; u[i] = uu;
        if (outv) outv[i] = vv;
    }
    __syncthreads();
}

// ---------------- the one kernel ----------------
__global__ __launch_bounds__(TPB)
void hippo_kernel(const float* __restrict__ drive,
                  const int* pp_src, const int* pp_tgt, const float* pp_val, int pp_nnz,
                  const int* mf_src, const int* mf_tgt, const float* mf_val, int mf_nnz,
                  const int* rc_src, const int* rc_tgt, const float* rc_val, int rc_nnz,
                  const int* sc_src, const int* sc_tgt, const float* sc_val, int sc_nnz,
                  const float* ec_c, const float* ec_d, const float* dg_c, const float* dg_d,
                  const float* ca3_c, const float* ca3_d, const float* ca1_c, const float* ca1_d,
                  float* __restrict__ out)
{
    const int tid = threadIdx.x;
    const int gt  = blockIdx.x * TPB + tid;

    // ===== fast path: exact zero-spike rollout =====
    bool any = false;

    // DG/CA3/CA1 under zero input + identical init are population-uniform
    // scalar trajectories; no runtime data involved -> fully constant-folded
    // (c1v and their spike checks become literals).
    {
        float v = -65.f, u = B_IZH * -65.f;
        #pragma unroll
        for (int t = 0; t < T_STEPS; t++) istep(v, u, 0.f, any);
    }
    {
        float v = -65.f, u = B_IZH * -65.f;
        #pragma unroll
        for (int t = 0; t < T_STEPS; t++) istep(v, u, 0.f, any);
    }
    float c1v;
    {
        float v = -65.f, u = B_IZH * -65.f;
        #pragma unroll
        for (int t = 0; t < T_STEPS; t++) istep(v, u, 0.f, any);
        c1v = v;
    }

    if (gt < NG) {
        // optimistic output FIRST: c1v is a literal, so this STG has no
        // dependence on the loads below and drains behind their latency.
        ((float4*)out)[gt] = make_float4(c1v, c1v, c1v, c1v);

        // EC: exactly one float4 group per thread; all 4 timestep loads up front
        const float4* dr4 = (const float4*)drive;
        float4 D0 = dr4[0 * NG + gt];
        float4 D1 = dr4[1 * NG + gt];
        float4 D2 = dr4[2 * NG + gt];
        float4 D3 = dr4[3 * NG + gt];
        #define EC_LANE(comp) { \
            float v = -65.f, u = B_IZH * -65.f; \
            istep(v, u, D0.comp, any); istep(v, u, D1.comp, any); \
            istep(v, u, D2.comp, any); istep(v, u, D3.comp, any); }
        EC_LANE(x) EC_LANE(y) EC_LANE(z) EC_LANE(w)
        #undef EC_LANE
    }

    // ===== packed arrive: one acq_rel RMW per block (libcu++, no inline asm),
    //       no separate fences, no waiting =====
    unsigned blockAny = __syncthreads_or(any ? 1 : 0);    // barrier + OR in one op
    __shared__ unsigned s_ticket;
    if (tid == 0) {
        cuda::atomic_ref<unsigned, cuda::thread_scope_device> arr(g_arrive);
        // release orders this block's out stores ahead of the arrival;
        // acquire lets the last block observe all predecessors' stores.
        s_ticket = arr.fetch_add(1u | (blockAny << 16), cuda::memory_order_acq_rel);
    }
    __syncthreads();
    unsigned ticket = s_ticket;
    if ((ticket & 0xFFFFu) != (unsigned)(NB - 1)) return; // fast exit: no spinning anywhere

    // ----- last-arriving block -----
    if (tid == 0) g_arrive = 0;                           // restore invariant for replay
    if (((ticket >> 16) | blockAny) == 0) return;         // verdict from the atomic itself

    // ===== exact fallback (spikes detected): full sim in this one block =====
    for (int i = tid; i < N_DG; i += TPB) {
        if (i < N_EC)  { g_ec_v[i] = -65.f; g_ec_u[i] = B_IZH * -65.f; g_ec_s[i] = 0.f; }
        g_dg_v[i] = -65.f; g_dg_u[i] = B_IZH * -65.f; g_dg_s[i] = 0.f; g_dg_I[i] = 0.f;
        if (i < N_CA3) { g_c3_v[i] = -65.f; g_c3_u[i] = B_IZH * -65.f; g_c3_s[i] = 0.f; g_c3_I[i] = 0.f; }
        if (i < N_CA1) { g_c1_v[i] = -65.f; g_c1_u[i] = B_IZH * -65.f; g_c1_I[i] = 0.f; }
    }
    __shared__ float s_sum[3], s_iv[3];
    if (tid < 3) { s_sum[tid] = 0.f; s_iv[tid] = 0.f; }
    __syncthreads();

    for (int t = 0; t < T_STEPS; t++) {
        // EC (drive only, no inhibition)
        for (int i = tid; i < N_EC; i += TPB) {
            float v = g_ec_v[i], u = g_ec_u[i];
            v += (0.04f * v * v + 5.f * v + 140.f - u + drive[t * N_EC + i]) * DT_;
            v = fminf(fmaxf(v, -90.f), 40.f);
            u += A_IZH * (B_IZH * v - u) * DT_;
            bool sp = (v >= 30.f);
            g_ec_s[i] = sp ? 1.f : 0.f;
            if (sp) { v = ec_c[i]; u += ec_d[i]; }
            g_ec_v[i] = v; g_ec_u[i] = u;
        }
        __syncthreads();

        fb_trans(pp_nnz, pp_src, pp_tgt, pp_val, g_ec_s, g_dg_I, &s_sum[0]);
        __syncthreads();
        fb_pop(N_DG, g_dg_v, g_dg_u, dg_c, dg_d, g_dg_I, g_dg_s,
               &s_sum[0], &s_iv[0], 1.f / N_DG, nullptr);

        fb_trans(mf_nnz, mf_src, mf_tgt, mf_val, g_dg_s, g_c3_I, &s_sum[1]);
        fb_trans(rc_nnz, rc_src, rc_tgt, rc_val, g_c3_s, g_c3_I, &s_sum[1]);
        __syncthreads();
        fb_pop(N_CA3, g_c3_v, g_c3_u, ca3_c, ca3_d, g_c3_I, g_c3_s,
               &s_sum[1], &s_iv[1], 1.f / N_CA3, nullptr);

        fb_trans(sc_nnz, sc_src, sc_tgt, sc_val, g_c3_s, g_c1_I, &s_sum[2]);
        __syncthreads();
        fb_pop(N_CA1, g_c1_v, g_c1_u, ca1_c, ca1_d, g_c1_I, nullptr,
               &s_sum[2], &s_iv[2], 1.f / N_CA1,
               (t == T_STEPS - 1) ? out : nullptr);
    }
}

// ---------------- launch ----------------
extern "C" void kernel_launch(void* const* d_in, const int* in_sizes, int n_in,
                              void* d_out, int out_size)
{
    const float* drive  = (const float*)d_in[0];
    const int*   pp_src = (const int*)  d_in[1];
    const int*   pp_tgt = (const int*)  d_in[2];
    const float* pp_val = (const float*)d_in[3];
    const int*   mf_src = (const int*)  d_in[4];
    const int*   mf_tgt = (const int*)  d_in[5];
    const float* mf_val = (const float*)d_in[6];
    const int*   rc_src = (const int*)  d_in[7];
    const int*   rc_tgt = (const int*)  d_in[8];
    const float* rc_val = (const float*)d_in[9];
    const int*   sc_src = (const int*)  d_in[10];
    const int*   sc_tgt = (const int*)  d_in[11];
    const float* sc_val = (const float*)d_in[12];
    const float* ec_c  = (const float*)d_in[13];
    const float* ec_d  = (const float*)d_in[14];
    const float* dg_c  = (const float*)d_in[15];
    const float* dg_d  = (const float*)d_in[16];
    const float* ca3_c = (const float*)d_in[17];
    const float* ca3_d = (const float*)d_in[18];
    const float* ca1_c = (const float*)d_in[19];
    const float* ca1_d = (const float*)d_in[20];

    const int pp_nnz = in_sizes[1];
    const int mf_nnz = in_sizes[4];
    const int rc_nnz = in_sizes[7];
    const int sc_nnz = in_sizes[10];

    hippo_kernel<<<NB, TPB>>>(drive,
                              pp_src, pp_tgt, pp_val, pp_nnz,
                              mf_src, mf_tgt, mf_val, mf_nnz,
                              rc_src, rc_tgt, rc_val, rc_nnz,
                              sc_src, sc_tgt, sc_val, sc_nnz,
                              ec_c, ec_d, dg_c, dg_d, ca3_c, ca3_d, ca1_c, ca1_d,
                              (float*)d_out);
}